// round 7
// baseline (speedup 1.0000x reference)
#include <cuda_runtime.h>
#include <math.h>

#define BB 512   // batch
#define TT 256   // time
#define FF 128   // features
#define HH 512   // hidden
#define NCTA 128

// ---------------- scratch (__device__ globals: allocation-free) ----------------
__device__ float g_gamma_h[(size_t)TT * BB * HH];   // [t][b][H]
__device__ float g_gamma_x[(size_t)BB * TT * FF];   // row-major (b*TT+t)
__device__ float g_alpha [(size_t)TT * BB * FF];    // [t][b][F]
__device__ float g_mf    [(size_t)BB * TT * FF];    // float(masks)
__device__ float g_h   [BB * HH];
__device__ float g_hdec[BB * HH];
__device__ float g_xc  [BB * FF];
// Pre-packed gates weights, tf32, mma-fragment order:
// index ((ny*16 + c8)*96 + k8)*32 + lane -> uint2 {b0, b1}
__device__ uint2 g_Bpack[16 * 16 * 96 * 32];
__device__ unsigned g_bar;

// ---------------- helpers ----------------
__device__ __forceinline__ unsigned f2tf32(float x) {
    unsigned r;
    asm("cvt.rna.tf32.f32 %0, %1;" : "=r"(r) : "f"(x));
    return r;
}
__device__ __forceinline__ void mma_tf32(float4& d,
    unsigned a0, unsigned a1, unsigned a2, unsigned a3,
    unsigned b0, unsigned b1)
{
    asm volatile(
        "mma.sync.aligned.m16n8k8.row.col.f32.tf32.tf32.f32 "
        "{%0,%1,%2,%3},{%4,%5,%6,%7},{%8,%9},{%0,%1,%2,%3};"
        : "+f"(d.x), "+f"(d.y), "+f"(d.z), "+f"(d.w)
        : "r"(a0), "r"(a1), "r"(a2), "r"(a3), "r"(b0), "r"(b1));
}
__device__ __forceinline__ float sigf(float x) { return 1.f / (1.f + __expf(-x)); }

// CG-style grid barrier: release (fence + atomic arrive) / acquire (ld.acquire poll)
__device__ __forceinline__ void gridbar(unsigned& tgt) {
    tgt += NCTA;
    __syncthreads();
    if (threadIdx.x == 0) {
        __threadfence();
        atomicAdd(&g_bar, 1u);
        unsigned v;
        do {
            asm volatile("ld.acquire.gpu.b32 %0, [%1];" : "=r"(v) : "l"(&g_bar) : "memory");
        } while (v < tgt);
    }
    __syncthreads();
}

// ---------------- K1: init + pack (all independent) ----------------
__global__ void init_pack_kernel(const int* __restrict__ masks,
                                 const float* __restrict__ W_ih,
                                 const float* __restrict__ W_hh)
{
    int bid = blockIdx.x, tid = threadIdx.x;
    int gidx = bid * 256 + tid;
    // pack B fragments (first 3072 blocks cover 786432 entries)
    if (bid < 3072) {
        int idx = gidx;
        int lane = idx & 31;
        int k8   = (idx >> 5) % 96;
        int c8   = ((idx >> 5) / 96) & 15;
        int ny   = (idx >> 5) / (96 * 16);
        int gID = lane >> 2, tg = lane & 3;
        int c = c8 * 8 + gID;
        int gcol = (c >> 5) * HH + ny * 32 + (c & 31);
        int k0 = k8 * 8 + tg;
        float w0, w1;
        if (k0 < 256) {
            w0 = W_ih[(size_t)gcol * 256 + k0];
            w1 = W_ih[(size_t)gcol * 256 + k0 + 4];
        } else {
            w0 = W_hh[(size_t)gcol * HH + (k0 - 256)];
            w1 = W_hh[(size_t)gcol * HH + (k0 - 252)];
        }
        g_Bpack[idx] = make_uint2(f2tf32(w0), f2tf32(w1));
    }
    int gsz = gridDim.x * 256;
    for (size_t i = gidx; i < (size_t)BB * TT * FF; i += gsz)
        g_mf[i] = (float)masks[i];
    for (int i = gidx; i < BB * HH; i += gsz) g_h[i] = 0.f;
    if (gidx == 0) g_bar = 0u;
}

// ---------------- precompute GEMM body (gamma_h, gamma_x, alpha) ----------------
template<int MODE, int N, int K>
__device__ __forceinline__ void pre_body(float (*As)[65], float (*Ws)[65],
                                         const float* __restrict__ A,
                                         const float* __restrict__ W,
                                         const float* __restrict__ bias, int n0)
{
    const float* baseA  = (MODE == 2) ? (const float*)g_gamma_x : A;
    const float* baseA2 = (MODE == 2) ? (const float*)g_mf      : A;
    int m0 = blockIdx.x * 64;
    int tid = threadIdx.x;
    int ty = tid >> 4, tx = tid & 15;
    float acc[4][4] = {};

    for (int k0 = 0; k0 < K; k0 += 64) {
        #pragma unroll
        for (int v = tid; v < 64 * 64 / 4; v += 256) {
            int r = v >> 4; int kq = (v & 15) * 4;
            int k = k0 + kq;
            const float* src = (k < 128) ? baseA : baseA2;
            int kk = (k < 128) ? k : (k - 128);
            float4 a = *(const float4*)&src[(size_t)(m0 + r) * 128 + kk];
            As[kq + 0][r] = a.x; As[kq + 1][r] = a.y;
            As[kq + 2][r] = a.z; As[kq + 3][r] = a.w;
        }
        #pragma unroll
        for (int v = tid; v < 64 * 64 / 4; v += 256) {
            int r = v >> 4; int kq = (v & 15) * 4;
            float4 w = *(const float4*)&W[(size_t)(n0 + r) * K + k0 + kq];
            Ws[kq + 0][r] = w.x; Ws[kq + 1][r] = w.y;
            Ws[kq + 2][r] = w.z; Ws[kq + 3][r] = w.w;
        }
        __syncthreads();
        #pragma unroll
        for (int kk = 0; kk < 64; kk++) {
            float a[4], w[4];
            #pragma unroll
            for (int i = 0; i < 4; i++) a[i] = As[kk][ty * 4 + i];
            #pragma unroll
            for (int j = 0; j < 4; j++) w[j] = Ws[kk][tx * 4 + j];
            #pragma unroll
            for (int i = 0; i < 4; i++)
                #pragma unroll
                for (int j = 0; j < 4; j++)
                    acc[i][j] += a[i] * w[j];
        }
        __syncthreads();
    }
    #pragma unroll
    for (int i = 0; i < 4; i++) {
        int m = m0 + ty * 4 + i;
        int b = m / TT, t = m % TT;
        #pragma unroll
        for (int j = 0; j < 4; j++) {
            int n = n0 + tx * 4 + j;
            float v = acc[i][j] + bias[n];
            if (MODE == 0)
                g_gamma_h[((size_t)t * BB + b) * HH + n] = expf(-fmaxf(v, 0.f));
            else if (MODE == 1)
                g_gamma_x[(size_t)m * FF + n] = expf(-fmaxf(v, 0.f));
            else
                g_alpha[((size_t)t * BB + b) * FF + n] = v;
        }
    }
}

// K2: gamma_h (by 0..7) + gamma_x (by 8..9), both K=128, A=deltas
__global__ void pre01_kernel(const float* __restrict__ deltas,
                             const float* __restrict__ W_dh, const float* __restrict__ b_dh,
                             const float* __restrict__ W_dx, const float* __restrict__ b_dx)
{
    __shared__ float As[64][65];
    __shared__ float Ws[64][65];
    if (blockIdx.y < 8) pre_body<0, HH, FF>(As, Ws, deltas, W_dh, b_dh, blockIdx.y * 64);
    else                pre_body<1, FF, FF>(As, Ws, deltas, W_dx, b_dx, (blockIdx.y - 8) * 64);
}

// K3: alpha (needs gamma_x)
__global__ void pre2_kernel(const float* __restrict__ W_wc, const float* __restrict__ b_wc)
{
    __shared__ float As[64][65];
    __shared__ float Ws[64][65];
    pre_body<2, FF, 2 * FF>(As, Ws, nullptr, W_wc, b_wc, blockIdx.y * 64);
}

// ---------------- phase-B A-chunk staging ----------------
__device__ __forceinline__ void stage_a_chunk(
    unsigned* __restrict__ buf, const float* __restrict__ out_cc,
    int kc, int m0, int t, int tid)
{
    int kbase = kc * 64;
    #pragma unroll
    for (int it = 0; it < 4; it++) {
        int idx = tid + it * 256;
        int m = idx >> 4; int kq = (idx & 15) * 4;
        int row = m0 + m;
        int k = kbase + kq;
        float4 a;
        if (kc < 2)
            a = __ldcg((const float4*)&out_cc[((size_t)row * TT + t) * FF + k]);
        else if (kc < 4)
            a = __ldg((const float4*)&g_mf[((size_t)row * TT + t) * FF + (k - 128)]);
        else
            a = __ldcg((const float4*)&g_hdec[(size_t)row * HH + (k - 256)]);
        uint4 u = make_uint4(f2tf32(a.x), f2tf32(a.y), f2tf32(a.z), f2tf32(a.w));
        *(uint4*)&buf[m * 68 + kq] = u;
    }
}

// ---------------- K4: persistent scan kernel (128 CTAs, 3 grid barriers/step) ----------------
// Phase A: CTA = 8 batch rows x 64-feature half; W_hr/W_fr slices resident in smem.
// Phase B: CTA = 64 rows x 32 hidden units x 4 gates; B frags LDG'd from g_Bpack; c in regs.
__global__ void __launch_bounds__(256, 1)
loop_kernel(const float* __restrict__ values,
            const float* __restrict__ W_hr, const float* __restrict__ b_hr,
            const float* __restrict__ W_fr, const float* __restrict__ b_fr,
            const float* __restrict__ b_ih, const float* __restrict__ b_hh,
            float* __restrict__ out)
{
    extern __shared__ float sdyn[];
    float* sWh  = sdyn;                        // 64 x 516
    float* sWf  = sdyn + 64 * 516;             // 64 x 132
    float* sScr = sdyn + 64 * 516 + 64 * 132;  // scratch: 8704 floats
    unsigned* sAs = (unsigned*)sScr;           // phase B: A double buffer 2x64x68
    float* sGs = sScr;                         // phase B epilogue alias [m][c] pad 129

    const int tid = threadIdx.x;
    const int bid = blockIdx.x;

    // phase-A ids
    const int fh  = bid & 1;
    const int r0g = (bid >> 1) * 8;
    const int fl  = tid & 63;
    const int fg  = fh * 64 + fl;
    const int rp  = tid >> 6;          // 0..3 (2 rows each)
    const int rA0 = r0g + rp * 2;

    // phase-B ids
    const int wid = tid >> 5, lane = tid & 31;
    const int gID = lane >> 2, tg = lane & 3;
    const int wm = wid >> 2, wc = wid & 3;
    const int m0 = (bid & 7) * 64;
    const int ny = bid >> 3;
    const int nEp = ny * 32 + lane;

    // resident weight slices (loaded once)
    for (int it = tid; it < 64 * 128; it += 256) {
        int ff = it >> 7; int kq = (it & 127) * 4;
        *(float4*)&sWh[ff * 516 + kq] = *(const float4*)&W_hr[(size_t)(fh * 64 + ff) * HH + kq];
    }
    for (int it = tid; it < 64 * 32; it += 256) {
        int ff = it >> 5; int kq = (it & 31) * 4;
        *(float4*)&sWf[ff * 132 + kq] = *(const float4*)&W_fr[(size_t)(fh * 64 + ff) * FF + kq];
    }

    // persistent per-thread state
    float c_state[8];
    #pragma unroll
    for (int j = 0; j < 8; j++) c_state[j] = 0.f;
    const float bhr = b_hr[fg];
    const float bfr = b_fr[fg];
    const float bi0 = b_ih[0 * HH + nEp] + b_hh[0 * HH + nEp];
    const float bi1 = b_ih[1 * HH + nEp] + b_hh[1 * HH + nEp];
    const float bi2 = b_ih[2 * HH + nEp] + b_hh[2 * HH + nEp];
    const float bi3 = b_ih[3 * HH + nEp] + b_hh[3 * HH + nEp];
    unsigned btgt = 0;
    __syncthreads();

    for (int t = 0; t < TT; t++) {
        // ================= phase A1: h_dec, x_h, x_c =================
        for (int it = tid; it < 1024; it += 256) {
            int i = it >> 7; int c = (it & 127) * 4;
            int row = r0g + i;
            float4 hv = __ldcg((const float4*)&g_h[(size_t)row * HH + c]);
            float4 gv = __ldg((const float4*)&g_gamma_h[((size_t)t * BB + row) * HH + c]);
            float4 o = make_float4(hv.x * gv.x, hv.y * gv.y, hv.z * gv.z, hv.w * gv.w);
            *(float4*)&sScr[i * 512 + c] = o;
            if (fh == 0) *(float4*)&g_hdec[(size_t)row * HH + c] = o;
        }
        __syncthreads();

        float acc0 = bhr, acc1 = bhr;
        #pragma unroll 8
        for (int k = 0; k < HH; k += 4) {
            float4 w  = *(const float4*)&sWh[fl * 516 + k];
            float4 h0 = *(const float4*)&sScr[(rp * 2) * 512 + k];
            float4 h1 = *(const float4*)&sScr[(rp * 2 + 1) * 512 + k];
            acc0 += h0.x * w.x + h0.y * w.y + h0.z * w.z + h0.w * w.w;
            acc1 += h1.x * w.x + h1.y * w.y + h1.z * w.z + h1.w * w.w;
        }
        size_t go0 = ((size_t)rA0 * TT + t) * FF + fg;
        size_t go1 = go0 + (size_t)TT * FF;
        float mm0 = __ldg(&g_mf[go0]), mm1 = __ldg(&g_mf[go1]);
        float xx0 = __ldg(&values[go0]), xx1 = __ldg(&values[go1]);
        float xh0 = acc0, xh1 = acc1;
        g_xc[(size_t)rA0 * FF + fg]       = mm0 * xx0 + (1.f - mm0) * xh0;
        g_xc[(size_t)(rA0 + 1) * FF + fg] = mm1 * xx1 + (1.f - mm1) * xh1;
        gridbar(btgt);

        // ================= phase A2: z_h, c_h, c_c =================
        {
            int i = tid >> 5; int c = (tid & 31) * 4;
            *(float4*)&sScr[i * 128 + c] =
                __ldcg((const float4*)&g_xc[(size_t)(r0g + i) * FF + c]);
        }
        __syncthreads();
        float az0 = bfr, az1 = bfr;
        #pragma unroll 8
        for (int k = 0; k < FF; k += 4) {
            float4 w  = *(const float4*)&sWf[fl * 132 + k];
            float4 x0 = *(const float4*)&sScr[(rp * 2) * 128 + k];
            float4 x1 = *(const float4*)&sScr[(rp * 2 + 1) * 128 + k];
            az0 += x0.x * w.x + x0.y * w.y + x0.z * w.z + x0.w * w.w;
            az1 += x1.x * w.x + x1.y * w.y + x1.z * w.z + x1.w * w.w;
        }
        float al0 = __ldg(&g_alpha[((size_t)t * BB + rA0) * FF + fg]);
        float al1 = __ldg(&g_alpha[((size_t)t * BB + rA0 + 1) * FF + fg]);
        float ch0 = al0 * az0 + (1.f - al0) * xh0;
        float ch1 = al1 * az1 + (1.f - al1) * xh1;
        out[go0] = mm0 * xx0 + (1.f - mm0) * ch0;
        out[go1] = mm1 * xx1 + (1.f - mm1) * ch1;
        gridbar(btgt);

        // ================= phase B: gates GEMM (tf32 mma) + LSTM =================
        float4 acc[2][4];
        #pragma unroll
        for (int i = 0; i < 2; i++)
            #pragma unroll
            for (int j = 0; j < 4; j++)
                acc[i][j] = make_float4(0.f, 0.f, 0.f, 0.f);

        stage_a_chunk(sAs, out, 0, m0, t, tid);
        __syncthreads();

        #pragma unroll 1
        for (int kc = 0; kc < 12; kc++) {
            const unsigned* As = sAs + (kc & 1) * (64 * 68);
            uint2 bf[8][4];
            {
                const uint2* bp = &g_Bpack[(((size_t)ny * 16 + wc * 4) * 96 + kc * 8) * 32 + lane];
                #pragma unroll
                for (int nf = 0; nf < 4; nf++)
                    #pragma unroll
                    for (int k8 = 0; k8 < 8; k8++)
                        bf[k8][nf] = __ldg(&bp[((size_t)nf * 96 + k8) * 32]);
            }
            if (kc < 11)
                stage_a_chunk(sAs + ((kc + 1) & 1) * (64 * 68), out, kc + 1, m0, t, tid);

            #pragma unroll
            for (int k8 = 0; k8 < 8; k8++) {
                int kk = k8 * 8;
                unsigned a[2][4];
                #pragma unroll
                for (int mf = 0; mf < 2; mf++) {
                    int r = wm * 32 + mf * 16 + gID;
                    a[mf][0] = As[(r    ) * 68 + kk + tg];
                    a[mf][1] = As[(r + 8) * 68 + kk + tg];
                    a[mf][2] = As[(r    ) * 68 + kk + tg + 4];
                    a[mf][3] = As[(r + 8) * 68 + kk + tg + 4];
                }
                #pragma unroll
                for (int nf = 0; nf < 4; nf++) {
                    mma_tf32(acc[0][nf], a[0][0], a[0][1], a[0][2], a[0][3],
                             bf[k8][nf].x, bf[k8][nf].y);
                    mma_tf32(acc[1][nf], a[1][0], a[1][1], a[1][2], a[1][3],
                             bf[k8][nf].x, bf[k8][nf].y);
                }
            }
            __syncthreads();
        }

        // exchange gates so each thread sees i,f,g,o for its (m, unit)
        #pragma unroll
        for (int mf = 0; mf < 2; mf++) {
            int rbase = wm * 32 + mf * 16 + gID;
            #pragma unroll
            for (int nf = 0; nf < 4; nf++) {
                int cbase = wc * 32 + nf * 8 + tg * 2;
                sGs[(rbase    ) * 129 + cbase    ] = acc[mf][nf].x;
                sGs[(rbase    ) * 129 + cbase + 1] = acc[mf][nf].y;
                sGs[(rbase + 8) * 129 + cbase    ] = acc[mf][nf].z;
                sGs[(rbase + 8) * 129 + cbase + 1] = acc[mf][nf].w;
            }
        }
        __syncthreads();

        // fused LSTM pointwise update; c lives in registers
        #pragma unroll
        for (int j = 0; j < 8; j++) {
            int ml = (tid >> 5) + 8 * j;
            float ig  = sigf(sGs[ml * 129 +  0 + lane] + bi0);
            float fgt = sigf(sGs[ml * 129 + 32 + lane] + bi1);
            float gg  = tanhf(sGs[ml * 129 + 64 + lane] + bi2);
            float og  = sigf(sGs[ml * 129 + 96 + lane] + bi3);
            float cn = fgt * c_state[j] + ig * gg;
            c_state[j] = cn;
            g_h[(size_t)(m0 + ml) * HH + nEp] = og * tanhf(cn);
        }
        gridbar(btgt);
    }
}

// ---------------- launch ----------------
extern "C" void kernel_launch(void* const* d_in, const int* in_sizes, int n_in,
                              void* d_out, int out_size)
{
    const float* values = (const float*)d_in[0];
    const int*   masks  = (const int*)  d_in[1];
    const float* deltas = (const float*)d_in[2];
    const float* W_dh = (const float*)d_in[3];
    const float* b_dh = (const float*)d_in[4];
    const float* W_dx = (const float*)d_in[5];
    const float* b_dx = (const float*)d_in[6];
    const float* W_hr = (const float*)d_in[7];
    const float* b_hr = (const float*)d_in[8];
    const float* W_fr = (const float*)d_in[9];
    const float* b_fr = (const float*)d_in[10];
    const float* W_wc = (const float*)d_in[11];
    const float* b_wc = (const float*)d_in[12];
    const float* W_ih = (const float*)d_in[13];
    const float* W_hh = (const float*)d_in[14];
    const float* b_ih = (const float*)d_in[15];
    const float* b_hh = (const float*)d_in[16];
    float* out = (float*)d_out;

    const int SMEM_BYTES = (64 * 516 + 64 * 132 + 8704) * 4;   // 200704
    cudaFuncSetAttribute(loop_kernel, cudaFuncAttributeMaxDynamicSharedMemorySize, SMEM_BYTES);

    init_pack_kernel<<<8192, 256>>>(masks, W_ih, W_hh);                       // launch 1
    pre01_kernel<<<dim3(2048, 10), 256>>>(deltas, W_dh, b_dh, W_dx, b_dx);    // launch 2
    pre2_kernel<<<dim3(2048, 2), 256>>>(W_wc, b_wc);                          // launch 3
    loop_kernel<<<NCTA, 256, SMEM_BYTES>>>(values, W_hr, b_hr, W_fr, b_fr,    // launch 4 (profiled)
                                           b_ih, b_hh, out);
}

// round 8
// speedup vs baseline: 1.2928x; 1.2928x over previous
#include <cuda_runtime.h>
#include <math.h>

#define BB 512   // batch
#define TT 256   // time
#define FF 128   // features
#define HH 512   // hidden
#define NCTA 128
#define NT 512   // threads per CTA (persistent kernel)

// ---------------- scratch (__device__ globals: allocation-free) ----------------
__device__ float g_gamma_h[(size_t)TT * BB * HH];   // [t][b][H]
__device__ float g_gamma_x[(size_t)BB * TT * FF];   // row-major (b*TT+t)
__device__ float g_alpha [(size_t)TT * BB * FF];    // [t][b][F]
__device__ float g_mf    [(size_t)BB * TT * FF];    // float(masks)
__device__ float g_h   [BB * HH];
__device__ float g_hdec[BB * HH];
__device__ float g_xc  [BB * FF];
// Pre-packed gates weights, tf32, mma-fragment order, k8 PAIRS per uint4:
// entry ((ny*16 + c8)*48 + k4)*32 + lane -> {b0(2k4), b1(2k4), b0(2k4+1), b1(2k4+1)}
__device__ uint4 g_Bpk[16 * 16 * 48 * 32];
__device__ unsigned g_bar;

// ---------------- helpers ----------------
__device__ __forceinline__ unsigned f2tf32(float x) {
    unsigned r;
    asm("cvt.rna.tf32.f32 %0, %1;" : "=r"(r) : "f"(x));
    return r;
}
__device__ __forceinline__ void mma_tf32(float4& d,
    unsigned a0, unsigned a1, unsigned a2, unsigned a3,
    unsigned b0, unsigned b1)
{
    asm volatile(
        "mma.sync.aligned.m16n8k8.row.col.f32.tf32.tf32.f32 "
        "{%0,%1,%2,%3},{%4,%5,%6,%7},{%8,%9},{%0,%1,%2,%3};"
        : "+f"(d.x), "+f"(d.y), "+f"(d.z), "+f"(d.w)
        : "r"(a0), "r"(a1), "r"(a2), "r"(a3), "r"(b0), "r"(b1));
}
__device__ __forceinline__ float sigf(float x) { return 1.f / (1.f + __expf(-x)); }

__device__ __forceinline__ void gridbar(unsigned& tgt) {
    tgt += NCTA;
    __syncthreads();
    if (threadIdx.x == 0) {
        __threadfence();
        atomicAdd(&g_bar, 1u);
        unsigned v;
        do {
            asm volatile("ld.acquire.gpu.b32 %0, [%1];" : "=r"(v) : "l"(&g_bar) : "memory");
        } while (v < tgt);
    }
    __syncthreads();
}

// ---------------- K1: init + pack ----------------
__global__ void init_pack_kernel(const int* __restrict__ masks,
                                 const float* __restrict__ W_ih,
                                 const float* __restrict__ W_hh)
{
    int bid = blockIdx.x, tid = threadIdx.x;
    int gidx = bid * 256 + tid;
    if (bid < 1536) {        // 393216 uint4 entries
        int idx = gidx;
        int lane = idx & 31;
        int k4   = (idx >> 5) % 48;
        int c8   = ((idx >> 5) / 48) & 15;
        int ny   = (idx >> 5) / (48 * 16);
        int gID = lane >> 2, tg = lane & 3;
        int c = c8 * 8 + gID;
        int gcol = (c >> 5) * HH + ny * 32 + (c & 31);
        float w[4];
        #pragma unroll
        for (int h = 0; h < 2; h++) {
            int k0 = (2 * k4 + h) * 8 + tg;
            if (k0 < 256) {
                w[2*h]   = W_ih[(size_t)gcol * 256 + k0];
                w[2*h+1] = W_ih[(size_t)gcol * 256 + k0 + 4];
            } else {
                w[2*h]   = W_hh[(size_t)gcol * HH + (k0 - 256)];
                w[2*h+1] = W_hh[(size_t)gcol * HH + (k0 - 252)];
            }
        }
        g_Bpk[idx] = make_uint4(f2tf32(w[0]), f2tf32(w[1]), f2tf32(w[2]), f2tf32(w[3]));
    }
    int gsz = gridDim.x * 256;
    for (size_t i = gidx; i < (size_t)BB * TT * FF; i += gsz)
        g_mf[i] = (float)masks[i];
    for (int i = gidx; i < BB * HH; i += gsz) g_h[i] = 0.f;
    if (gidx == 0) g_bar = 0u;
}

// ---------------- precompute GEMM body (gamma_h, gamma_x, alpha) ----------------
template<int MODE, int N, int K>
__device__ __forceinline__ void pre_body(float (*As)[65], float (*Ws)[65],
                                         const float* __restrict__ A,
                                         const float* __restrict__ W,
                                         const float* __restrict__ bias, int n0)
{
    const float* baseA  = (MODE == 2) ? (const float*)g_gamma_x : A;
    const float* baseA2 = (MODE == 2) ? (const float*)g_mf      : A;
    int m0 = blockIdx.x * 64;
    int tid = threadIdx.x;
    int ty = tid >> 4, tx = tid & 15;
    float acc[4][4] = {};

    for (int k0 = 0; k0 < K; k0 += 64) {
        #pragma unroll
        for (int v = tid; v < 64 * 64 / 4; v += 256) {
            int r = v >> 4; int kq = (v & 15) * 4;
            int k = k0 + kq;
            const float* src = (k < 128) ? baseA : baseA2;
            int kk = (k < 128) ? k : (k - 128);
            float4 a = *(const float4*)&src[(size_t)(m0 + r) * 128 + kk];
            As[kq + 0][r] = a.x; As[kq + 1][r] = a.y;
            As[kq + 2][r] = a.z; As[kq + 3][r] = a.w;
        }
        #pragma unroll
        for (int v = tid; v < 64 * 64 / 4; v += 256) {
            int r = v >> 4; int kq = (v & 15) * 4;
            float4 w = *(const float4*)&W[(size_t)(n0 + r) * K + k0 + kq];
            Ws[kq + 0][r] = w.x; Ws[kq + 1][r] = w.y;
            Ws[kq + 2][r] = w.z; Ws[kq + 3][r] = w.w;
        }
        __syncthreads();
        #pragma unroll
        for (int kk = 0; kk < 64; kk++) {
            float a[4], w[4];
            #pragma unroll
            for (int i = 0; i < 4; i++) a[i] = As[kk][ty * 4 + i];
            #pragma unroll
            for (int j = 0; j < 4; j++) w[j] = Ws[kk][tx * 4 + j];
            #pragma unroll
            for (int i = 0; i < 4; i++)
                #pragma unroll
                for (int j = 0; j < 4; j++)
                    acc[i][j] += a[i] * w[j];
        }
        __syncthreads();
    }
    #pragma unroll
    for (int i = 0; i < 4; i++) {
        int m = m0 + ty * 4 + i;
        int b = m / TT, t = m % TT;
        #pragma unroll
        for (int j = 0; j < 4; j++) {
            int n = n0 + tx * 4 + j;
            float v = acc[i][j] + bias[n];
            if (MODE == 0)
                g_gamma_h[((size_t)t * BB + b) * HH + n] = expf(-fmaxf(v, 0.f));
            else if (MODE == 1)
                g_gamma_x[(size_t)m * FF + n] = expf(-fmaxf(v, 0.f));
            else
                g_alpha[((size_t)t * BB + b) * FF + n] = v;
        }
    }
}

__global__ void pre01_kernel(const float* __restrict__ deltas,
                             const float* __restrict__ W_dh, const float* __restrict__ b_dh,
                             const float* __restrict__ W_dx, const float* __restrict__ b_dx)
{
    __shared__ float As[64][65];
    __shared__ float Ws[64][65];
    if (blockIdx.y < 8) pre_body<0, HH, FF>(As, Ws, deltas, W_dh, b_dh, blockIdx.y * 64);
    else                pre_body<1, FF, FF>(As, Ws, deltas, W_dx, b_dx, (blockIdx.y - 8) * 64);
}

__global__ void pre2_kernel(const float* __restrict__ W_wc, const float* __restrict__ b_wc)
{
    __shared__ float As[64][65];
    __shared__ float Ws[64][65];
    pre_body<2, FF, 2 * FF>(As, Ws, nullptr, W_wc, b_wc, blockIdx.y * 64);
}

// ---------------- phase-B A-chunk staging (512 threads) ----------------
__device__ __forceinline__ void stage_a_chunk(
    unsigned* __restrict__ buf, const float* __restrict__ out_cc,
    int kc, int m0, int t, int tid)
{
    int kbase = kc * 64;
    #pragma unroll
    for (int it = 0; it < 2; it++) {
        int idx = tid + it * NT;
        int m = idx >> 4; int kq = (idx & 15) * 4;
        int row = m0 + m;
        int k = kbase + kq;
        float4 a;
        if (kc < 2)
            a = __ldcg((const float4*)&out_cc[((size_t)row * TT + t) * FF + k]);
        else if (kc < 4)
            a = __ldg((const float4*)&g_mf[((size_t)row * TT + t) * FF + (k - 128)]);
        else
            a = __ldcg((const float4*)&g_hdec[(size_t)row * HH + (k - 256)]);
        uint4 u = make_uint4(f2tf32(a.x), f2tf32(a.y), f2tf32(a.z), f2tf32(a.w));
        *(uint4*)&buf[m * 68 + kq] = u;
    }
}

// ---------------- K4: persistent scan kernel (128 CTAs x 512 thr) ----------------
// Phase A1: CTA = 8 rows x 64-f half; thread = (f, k-slice of 64), 8 row-accs,
//           reduce via smem. W_hr slice resident in smem.
// Phase A2: same rows; z_h over K=128 with thread = (f, k-slice of 16). W_fr resident.
// Phase B : CTA = 64 rows x 128 gate-cols; 16 warps as 2wm x 8wc; B frags from
//           g_Bpk via LDG.128 (k8-pairs); c-state in registers.
__global__ void __launch_bounds__(NT, 1)
loop_kernel(const float* __restrict__ values,
            const float* __restrict__ W_hr, const float* __restrict__ b_hr,
            const float* __restrict__ W_fr, const float* __restrict__ b_fr,
            const float* __restrict__ b_ih, const float* __restrict__ b_hh,
            float* __restrict__ out)
{
    extern __shared__ float sdyn[];
    float* sWh  = sdyn;                        // 64 x 516
    float* sWf  = sdyn + 64 * 516;             // 64 x 132
    float* sScr = sdyn + 64 * 516 + 64 * 132;  // scratch: 8704 floats
    unsigned* sAs = (unsigned*)sScr;           // phase B: A double buffer 2x64x68
    float* sGs = sScr;                         // phase B epilogue alias [m][c] pad 129
    float* sRed = sScr + 4096;                 // phase A reduction buffer (4096)

    const int tid = threadIdx.x;
    const int bid = blockIdx.x;

    // phase-A ids
    const int fh  = bid & 1;            // feature half
    const int r0g = (bid >> 1) * 8;     // 8 batch rows
    const int fl  = tid & 63;           // local feature
    const int kq  = tid >> 6;           // k-slice id (0..7)
    const int rO  = tid >> 6;           // output row (reduce mapping, 0..7)
    const int fg  = fh * 64 + fl;

    // phase-B ids
    const int wid = tid >> 5, lane = tid & 31;
    const int gID = lane >> 2, tg = lane & 3;
    const int wm = wid >> 3, wc = wid & 7;     // 2 x 8
    const int m0 = (bid & 7) * 64;
    const int ny = bid >> 3;
    const int nEp = ny * 32 + lane;

    // resident weight slices (loaded once)
    for (int it = tid; it < 64 * 128; it += NT) {
        int ff = it >> 7; int kk4 = (it & 127) * 4;
        *(float4*)&sWh[ff * 516 + kk4] = *(const float4*)&W_hr[(size_t)(fh * 64 + ff) * HH + kk4];
    }
    for (int it = tid; it < 64 * 32; it += NT) {
        int ff = it >> 5; int kk4 = (it & 31) * 4;
        *(float4*)&sWf[ff * 132 + kk4] = *(const float4*)&W_fr[(size_t)(fh * 64 + ff) * FF + kk4];
    }

    // persistent per-thread state
    float c_state[4];
    #pragma unroll
    for (int j = 0; j < 4; j++) c_state[j] = 0.f;
    const float bhr = b_hr[fg];
    const float bfr = b_fr[fg];
    const float bi0 = b_ih[0 * HH + nEp] + b_hh[0 * HH + nEp];
    const float bi1 = b_ih[1 * HH + nEp] + b_hh[1 * HH + nEp];
    const float bi2 = b_ih[2 * HH + nEp] + b_hh[2 * HH + nEp];
    const float bi3 = b_ih[3 * HH + nEp] + b_hh[3 * HH + nEp];
    unsigned btgt = 0;
    __syncthreads();

    for (int t = 0; t < TT; t++) {
        // ================= phase A1: h_dec, x_h, x_c =================
        #pragma unroll
        for (int it = tid; it < 1024; it += NT) {
            int i = it >> 7; int c = (it & 127) * 4;
            int row = r0g + i;
            float4 hv = __ldcg((const float4*)&g_h[(size_t)row * HH + c]);
            float4 gv = __ldg((const float4*)&g_gamma_h[((size_t)t * BB + row) * HH + c]);
            float4 o = make_float4(hv.x * gv.x, hv.y * gv.y, hv.z * gv.z, hv.w * gv.w);
            *(float4*)&sScr[i * 512 + c] = o;
            if (fh == 0) *(float4*)&g_hdec[(size_t)row * HH + c] = o;
        }
        __syncthreads();

        // thread (fl, kq): partial x_h over k-slice [kq*64, kq*64+64) for all 8 rows
        {
            float accs[8];
            #pragma unroll
            for (int r = 0; r < 8; r++) accs[r] = 0.f;
            const int kb = kq * 64;
            #pragma unroll
            for (int kk = 0; kk < 64; kk += 4) {
                float4 w = *(const float4*)&sWh[fl * 516 + kb + kk];
                #pragma unroll
                for (int r = 0; r < 8; r++) {
                    float4 h = *(const float4*)&sScr[r * 512 + kb + kk];
                    accs[r] += h.x * w.x + h.y * w.y + h.z * w.z + h.w * w.w;
                }
            }
            #pragma unroll
            for (int r = 0; r < 8; r++)
                sRed[kq * 512 + r * 64 + fl] = accs[r];
        }
        __syncthreads();

        float xh, m_, x_;
        size_t gofs;
        {
            xh = bhr;
            #pragma unroll
            for (int q = 0; q < 8; q++) xh += sRed[q * 512 + rO * 64 + fl];
            int row = r0g + rO;
            gofs = ((size_t)row * TT + t) * FF + fg;
            m_ = __ldg(&g_mf[gofs]);
            x_ = __ldg(&values[gofs]);
            g_xc[(size_t)row * FF + fg] = m_ * x_ + (1.f - m_) * xh;
        }
        gridbar(btgt);

        // ================= phase A2: z_h, c_h, c_c =================
        #pragma unroll
        for (int it = tid; it < 1024; it += NT) {
            int i = it >> 7; int c = it & 127;
            sScr[i * 128 + c] = __ldcg(&g_xc[(size_t)(r0g + i) * FF + c]);
        }
        __syncthreads();
        {
            float acz[8];
            #pragma unroll
            for (int r = 0; r < 8; r++) acz[r] = 0.f;
            const int kb = kq * 16;
            #pragma unroll
            for (int kk = 0; kk < 16; kk += 4) {
                float4 w = *(const float4*)&sWf[fl * 132 + kb + kk];
                #pragma unroll
                for (int r = 0; r < 8; r++) {
                    float4 xv = *(const float4*)&sScr[r * 128 + kb + kk];
                    acz[r] += xv.x * w.x + xv.y * w.y + xv.z * w.z + xv.w * w.w;
                }
            }
            #pragma unroll
            for (int r = 0; r < 8; r++)
                sRed[kq * 512 + r * 64 + fl] = acz[r];
        }
        __syncthreads();
        {
            float zh = bfr;
            #pragma unroll
            for (int q = 0; q < 8; q++) zh += sRed[q * 512 + rO * 64 + fl];
            float al = __ldg(&g_alpha[((size_t)t * BB + (r0g + rO)) * FF + fg]);
            float ch = al * zh + (1.f - al) * xh;
            out[gofs] = m_ * x_ + (1.f - m_) * ch;
        }
        gridbar(btgt);

        // ================= phase B: gates GEMM (tf32 mma) + LSTM =================
        float4 acc[2][2];
        #pragma unroll
        for (int i = 0; i < 2; i++)
            #pragma unroll
            for (int j = 0; j < 2; j++)
                acc[i][j] = make_float4(0.f, 0.f, 0.f, 0.f);

        stage_a_chunk(sAs, out, 0, m0, t, tid);
        __syncthreads();

        #pragma unroll 1
        for (int kc = 0; kc < 12; kc++) {
            const unsigned* As = sAs + (kc & 1) * (64 * 68);

            // B fragments: 8 x LDG.128 per thread (k8-pairs)
            uint4 bf[2][4];
            {
                const uint4* bp = &g_Bpk[(((size_t)ny * 16 + wc * 2) * 48 + kc * 4) * 32 + lane];
                #pragma unroll
                for (int nf = 0; nf < 2; nf++)
                    #pragma unroll
                    for (int k4 = 0; k4 < 4; k4++)
                        bf[nf][k4] = __ldg(&bp[(size_t)nf * (48 * 32) + k4 * 32]);
            }
            if (kc < 11)
                stage_a_chunk(sAs + ((kc + 1) & 1) * (64 * 68), out, kc + 1, m0, t, tid);

            #pragma unroll
            for (int k8 = 0; k8 < 8; k8++) {
                int kk = k8 * 8;
                unsigned a[2][4];
                #pragma unroll
                for (int mf = 0; mf < 2; mf++) {
                    int r = wm * 32 + mf * 16 + gID;
                    a[mf][0] = As[(r    ) * 68 + kk + tg];
                    a[mf][1] = As[(r + 8) * 68 + kk + tg];
                    a[mf][2] = As[(r    ) * 68 + kk + tg + 4];
                    a[mf][3] = As[(r + 8) * 68 + kk + tg + 4];
                }
                int k4 = k8 >> 1;
                bool hi = (k8 & 1) != 0;
                #pragma unroll
                for (int nf = 0; nf < 2; nf++) {
                    unsigned b0 = hi ? bf[nf][k4].z : bf[nf][k4].x;
                    unsigned b1 = hi ? bf[nf][k4].w : bf[nf][k4].y;
                    mma_tf32(acc[0][nf], a[0][0], a[0][1], a[0][2], a[0][3], b0, b1);
                    mma_tf32(acc[1][nf], a[1][0], a[1][1], a[1][2], a[1][3], b0, b1);
                }
            }
            __syncthreads();
        }

        // exchange gates so each thread sees i,f,g,o for its (m, unit)
        #pragma unroll
        for (int mf = 0; mf < 2; mf++) {
            int rbase = wm * 32 + mf * 16 + gID;
            #pragma unroll
            for (int nf = 0; nf < 2; nf++) {
                int cbase = wc * 16 + nf * 8 + tg * 2;
                sGs[(rbase    ) * 129 + cbase    ] = acc[mf][nf].x;
                sGs[(rbase    ) * 129 + cbase + 1] = acc[mf][nf].y;
                sGs[(rbase + 8) * 129 + cbase    ] = acc[mf][nf].z;
                sGs[(rbase + 8) * 129 + cbase + 1] = acc[mf][nf].w;
            }
        }
        __syncthreads();

        // fused LSTM pointwise update; c lives in registers
        #pragma unroll
        for (int j = 0; j < 4; j++) {
            int ml = wid + 16 * j;
            float ig  = sigf(sGs[ml * 129 +  0 + lane] + bi0);
            float fgt = sigf(sGs[ml * 129 + 32 + lane] + bi1);
            float gg  = tanhf(sGs[ml * 129 + 64 + lane] + bi2);
            float og  = sigf(sGs[ml * 129 + 96 + lane] + bi3);
            float cn = fgt * c_state[j] + ig * gg;
            c_state[j] = cn;
            g_h[(size_t)(m0 + ml) * HH + nEp] = og * tanhf(cn);
        }
        gridbar(btgt);
    }
}

// ---------------- launch ----------------
extern "C" void kernel_launch(void* const* d_in, const int* in_sizes, int n_in,
                              void* d_out, int out_size)
{
    const float* values = (const float*)d_in[0];
    const int*   masks  = (const int*)  d_in[1];
    const float* deltas = (const float*)d_in[2];
    const float* W_dh = (const float*)d_in[3];
    const float* b_dh = (const float*)d_in[4];
    const float* W_dx = (const float*)d_in[5];
    const float* b_dx = (const float*)d_in[6];
    const float* W_hr = (const float*)d_in[7];
    const float* b_hr = (const float*)d_in[8];
    const float* W_fr = (const float*)d_in[9];
    const float* b_fr = (const float*)d_in[10];
    const float* W_wc = (const float*)d_in[11];
    const float* b_wc = (const float*)d_in[12];
    const float* W_ih = (const float*)d_in[13];
    const float* W_hh = (const float*)d_in[14];
    const float* b_ih = (const float*)d_in[15];
    const float* b_hh = (const float*)d_in[16];
    float* out = (float*)d_out;

    const int SMEM_BYTES = (64 * 516 + 64 * 132 + 8704) * 4;   // 200704
    cudaFuncSetAttribute(loop_kernel, cudaFuncAttributeMaxDynamicSharedMemorySize, SMEM_BYTES);

    init_pack_kernel<<<8192, 256>>>(masks, W_ih, W_hh);                       // launch 1
    pre01_kernel<<<dim3(2048, 10), 256>>>(deltas, W_dh, b_dh, W_dx, b_dx);    // launch 2
    pre2_kernel<<<dim3(2048, 2), 256>>>(W_wc, b_wc);                          // launch 3
    loop_kernel<<<NCTA, NT, SMEM_BYTES>>>(values, W_hr, b_hr, W_fr, b_fr,     // launch 4 (profiled)
                                          b_ih, b_hh, out);
}

// round 11
// speedup vs baseline: 1.5991x; 1.2370x over previous
#include <cuda_runtime.h>
#include <math.h>

#define BB 512   // batch
#define TT 256   // time
#define FF 128   // features
#define HH 512   // hidden
#define NCTA 128
#define NT 512   // threads per CTA (persistent kernel)

// ---------------- scratch (__device__ globals: allocation-free) ----------------
__device__ float g_gamma_h[(size_t)TT * BB * HH];   // [t][b][H]
__device__ float g_gamma_x[(size_t)BB * TT * FF];   // row-major (b*TT+t)
__device__ float g_alpha [(size_t)TT * BB * FF];    // [t][b][F]
__device__ float g_mf    [(size_t)BB * TT * FF];    // float(masks)
__device__ float g_h   [BB * HH];
__device__ float g_hdec[BB * HH];
__device__ float g_xc  [BB * FF];
// Pre-packed gates weights, bf16, m16n8k16 fragment order, 2 k-steps per uint4:
// entry ((ny*16 + c8)*24 + kq32)*32 + lane -> {b0(s), b1(s), b0(s+1), b1(s+1)}, s=2*kq32
__device__ uint4 g_Bpk[16 * 16 * 24 * 32];
__device__ unsigned g_bar;

// ---------------- helpers ----------------
__device__ __forceinline__ unsigned pack_bf16(float lo, float hi) {
    unsigned r;
    asm("cvt.rn.bf16x2.f32 %0, %1, %2;" : "=r"(r) : "f"(hi), "f"(lo));
    return r;
}
__device__ __forceinline__ void mma_bf16(float4& d,
    unsigned a0, unsigned a1, unsigned a2, unsigned a3,
    unsigned b0, unsigned b1)
{
    asm volatile(
        "mma.sync.aligned.m16n8k16.row.col.f32.bf16.bf16.f32 "
        "{%0,%1,%2,%3},{%4,%5,%6,%7},{%8,%9},{%0,%1,%2,%3};"
        : "+f"(d.x), "+f"(d.y), "+f"(d.z), "+f"(d.w)
        : "r"(a0), "r"(a1), "r"(a2), "r"(a3), "r"(b0), "r"(b1));
}
__device__ __forceinline__ float sigf(float x) { return 1.f / (1.f + __expf(-x)); }

__device__ __forceinline__ void gridbar(unsigned& tgt) {
    tgt += NCTA;
    __syncthreads();
    if (threadIdx.x == 0) {
        __threadfence();
        atomicAdd(&g_bar, 1u);
        unsigned v;
        do {
            asm volatile("ld.acquire.gpu.b32 %0, [%1];" : "=r"(v) : "l"(&g_bar) : "memory");
        } while (v < tgt);
    }
    __syncthreads();
}

// ---------------- K1: init + pack ----------------
__global__ void init_pack_kernel(const int* __restrict__ masks,
                                 const float* __restrict__ W_ih,
                                 const float* __restrict__ W_hh)
{
    int bid = blockIdx.x, tid = threadIdx.x;
    int gidx = bid * 256 + tid;
    if (gidx < 16 * 16 * 24 * 32) {   // 196608 uint4 entries
        int idx = gidx;
        int lane = idx & 31;
        int kq32 = (idx >> 5) % 24;
        int c8   = ((idx >> 5) / 24) & 15;
        int ny   = (idx >> 5) / (24 * 16);
        int gID = lane >> 2, tg = lane & 3;
        int c = c8 * 8 + gID;
        int gcol = (c >> 5) * HH + ny * 32 + (c & 31);
        unsigned u[4];
        #pragma unroll
        for (int h = 0; h < 2; h++) {
            int kb = (2 * kq32 + h) * 16;
            #pragma unroll
            for (int p = 0; p < 2; p++) {       // p=0 -> b0 (k 2tg), p=1 -> b1 (k 2tg+8)
                int k0 = kb + 2 * tg + p * 8;
                float w0, w1;
                if (k0 < 256) {
                    w0 = W_ih[(size_t)gcol * 256 + k0];
                    w1 = W_ih[(size_t)gcol * 256 + k0 + 1];
                } else {
                    w0 = W_hh[(size_t)gcol * HH + (k0 - 256)];
                    w1 = W_hh[(size_t)gcol * HH + (k0 - 255)];
                }
                u[h * 2 + p] = pack_bf16(w0, w1);
            }
        }
        g_Bpk[idx] = make_uint4(u[0], u[1], u[2], u[3]);
    }
    int gsz = gridDim.x * 256;
    for (size_t i = gidx; i < (size_t)BB * TT * FF; i += gsz)
        g_mf[i] = (float)masks[i];
    for (int i = gidx; i < BB * HH; i += gsz) g_h[i] = 0.f;
    if (gidx == 0) g_bar = 0u;
}

// ---------------- precompute GEMM body (gamma_h, gamma_x, alpha) ----------------
template<int MODE, int N, int K>
__device__ __forceinline__ void pre_body(float (*As)[65], float (*Ws)[65],
                                         const float* __restrict__ A,
                                         const float* __restrict__ W,
                                         const float* __restrict__ bias, int n0)
{
    const float* baseA  = (MODE == 2) ? (const float*)g_gamma_x : A;
    const float* baseA2 = (MODE == 2) ? (const float*)g_mf      : A;
    int m0 = blockIdx.x * 64;
    int tid = threadIdx.x;
    int ty = tid >> 4, tx = tid & 15;
    float acc[4][4] = {};

    for (int k0 = 0; k0 < K; k0 += 64) {
        #pragma unroll
        for (int v = tid; v < 64 * 64 / 4; v += 256) {
            int r = v >> 4; int kq = (v & 15) * 4;
            int k = k0 + kq;
            const float* src = (k < 128) ? baseA : baseA2;
            int kk = (k < 128) ? k : (k - 128);
            float4 a = *(const float4*)&src[(size_t)(m0 + r) * 128 + kk];
            As[kq + 0][r] = a.x; As[kq + 1][r] = a.y;
            As[kq + 2][r] = a.z; As[kq + 3][r] = a.w;
        }
        #pragma unroll
        for (int v = tid; v < 64 * 64 / 4; v += 256) {
            int r = v >> 4; int kq = (v & 15) * 4;
            float4 w = *(const float4*)&W[(size_t)(n0 + r) * K + k0 + kq];
            Ws[kq + 0][r] = w.x; Ws[kq + 1][r] = w.y;
            Ws[kq + 2][r] = w.z; Ws[kq + 3][r] = w.w;
        }
        __syncthreads();
        #pragma unroll
        for (int kk = 0; kk < 64; kk++) {
            float a[4], w[4];
            #pragma unroll
            for (int i = 0; i < 4; i++) a[i] = As[kk][ty * 4 + i];
            #pragma unroll
            for (int j = 0; j < 4; j++) w[j] = Ws[kk][tx * 4 + j];
            #pragma unroll
            for (int i = 0; i < 4; i++)
                #pragma unroll
                for (int j = 0; j < 4; j++)
                    acc[i][j] += a[i] * w[j];
        }
        __syncthreads();
    }
    #pragma unroll
    for (int i = 0; i < 4; i++) {
        int m = m0 + ty * 4 + i;
        int b = m / TT, t = m % TT;
        #pragma unroll
        for (int j = 0; j < 4; j++) {
            int n = n0 + tx * 4 + j;
            float v = acc[i][j] + bias[n];
            if (MODE == 0)
                g_gamma_h[((size_t)t * BB + b) * HH + n] = expf(-fmaxf(v, 0.f));
            else if (MODE == 1)
                g_gamma_x[(size_t)m * FF + n] = expf(-fmaxf(v, 0.f));
            else
                g_alpha[((size_t)t * BB + b) * FF + n] = v;
        }
    }
}

__global__ void pre01_kernel(const float* __restrict__ deltas,
                             const float* __restrict__ W_dh, const float* __restrict__ b_dh,
                             const float* __restrict__ W_dx, const float* __restrict__ b_dx)
{
    __shared__ float As[64][65];
    __shared__ float Ws[64][65];
    if (blockIdx.y < 8) pre_body<0, HH, FF>(As, Ws, deltas, W_dh, b_dh, blockIdx.y * 64);
    else                pre_body<1, FF, FF>(As, Ws, deltas, W_dx, b_dx, (blockIdx.y - 8) * 64);
}

__global__ void pre2_kernel(const float* __restrict__ W_wc, const float* __restrict__ b_wc)
{
    __shared__ float As[64][65];
    __shared__ float Ws[64][65];
    pre_body<2, FF, 2 * FF>(As, Ws, nullptr, W_wc, b_wc, blockIdx.y * 64);
}

// ---------------- phase-B A-chunk staging (bf16, 512 threads) ----------------
// Each thread converts 8 floats -> 1 uint4 (8 bf16). As row stride = 36 u32 (32 + pad).
__device__ __forceinline__ void stage_a_chunk(
    unsigned* __restrict__ buf, const float* __restrict__ out_cc,
    int kc, int m0, int t, int tid)
{
    int m = tid >> 3;            // 0..63
    int kq = (tid & 7) * 8;      // float offset within chunk
    int row = m0 + m;
    int k = kc * 64 + kq;
    const float* src;
    size_t ofs;
    if (kc < 2)      { src = out_cc; ofs = ((size_t)row * TT + t) * FF + k; }
    else if (kc < 4) { src = g_mf;   ofs = ((size_t)row * TT + t) * FF + (k - 128); }
    else             { src = g_hdec; ofs = (size_t)row * HH + (k - 256); }
    float4 a = __ldcg((const float4*)&src[ofs]);
    float4 b = __ldcg((const float4*)&src[ofs + 4]);
    uint4 u = make_uint4(pack_bf16(a.x, a.y), pack_bf16(a.z, a.w),
                         pack_bf16(b.x, b.y), pack_bf16(b.z, b.w));
    *(uint4*)&buf[m * 36 + (kq >> 1)] = u;
}

// ---------------- K4: persistent scan kernel (128 CTAs x 512 thr) ----------------
// Phase A1: CTA = 8 rows x 64-f half; thread = (f, k-slice of 64), reduce via smem.
// Phase A2: z_h over K=128, thread = (f, k-slice of 16).
// Phase B : CTA = 64 rows x 128 gate-cols; 16 warps as 2wm x 8wc; bf16 m16n8k16 mma;
//           B frags from g_Bpk via LDG.128; c-state in registers.
__global__ void __launch_bounds__(NT, 1)
loop_kernel(const float* __restrict__ values,
            const float* __restrict__ W_hr, const float* __restrict__ b_hr,
            const float* __restrict__ W_fr, const float* __restrict__ b_fr,
            const float* __restrict__ b_ih, const float* __restrict__ b_hh,
            float* __restrict__ out)
{
    extern __shared__ float sdyn[];
    float* sWh  = sdyn;                        // 64 x 516
    float* sWf  = sdyn + 64 * 516;             // 64 x 132
    float* sScr = sdyn + 64 * 516 + 64 * 132;  // scratch: 8704 floats
    unsigned* sAs = (unsigned*)sScr;           // phase B: A double buffer 2 x 64 x 36 u32
    float* sGs = sScr;                         // phase B epilogue alias [m][c] pad 129
    float* sRed = sScr + 4096;                 // phase A reduction buffer (4096)

    const int tid = threadIdx.x;
    const int bid = blockIdx.x;

    // phase-A ids
    const int fh  = bid & 1;            // feature half
    const int r0g = (bid >> 1) * 8;     // 8 batch rows
    const int fl  = tid & 63;           // local feature
    const int kq  = tid >> 6;           // k-slice id (0..7)
    const int rO  = tid >> 6;           // output row (reduce mapping, 0..7)
    const int fg  = fh * 64 + fl;

    // phase-B ids
    const int wid = tid >> 5, lane = tid & 31;
    const int gID = lane >> 2, tg = lane & 3;
    const int wm = wid >> 3, wc = wid & 7;     // 2 x 8
    const int m0 = (bid & 7) * 64;
    const int ny = bid >> 3;
    const int nEp = ny * 32 + lane;

    // resident weight slices (loaded once)
    for (int it = tid; it < 64 * 128; it += NT) {
        int ff = it >> 7; int kk4 = (it & 127) * 4;
        *(float4*)&sWh[ff * 516 + kk4] = *(const float4*)&W_hr[(size_t)(fh * 64 + ff) * HH + kk4];
    }
    for (int it = tid; it < 64 * 32; it += NT) {
        int ff = it >> 5; int kk4 = (it & 31) * 4;
        *(float4*)&sWf[ff * 132 + kk4] = *(const float4*)&W_fr[(size_t)(fh * 64 + ff) * FF + kk4];
    }

    // persistent per-thread state
    float c_state[4];
    #pragma unroll
    for (int j = 0; j < 4; j++) c_state[j] = 0.f;
    const float bhr = b_hr[fg];
    const float bfr = b_fr[fg];
    const float bi0 = b_ih[0 * HH + nEp] + b_hh[0 * HH + nEp];
    const float bi1 = b_ih[1 * HH + nEp] + b_hh[1 * HH + nEp];
    const float bi2 = b_ih[2 * HH + nEp] + b_hh[2 * HH + nEp];
    const float bi3 = b_ih[3 * HH + nEp] + b_hh[3 * HH + nEp];
    unsigned btgt = 0;
    __syncthreads();

    for (int t = 0; t < TT; t++) {
        // ================= phase A1: h_dec, x_h, x_c =================
        #pragma unroll
        for (int it = tid; it < 1024; it += NT) {
            int i = it >> 7; int c = (it & 127) * 4;
            int row = r0g + i;
            float4 hv = __ldcg((const float4*)&g_h[(size_t)row * HH + c]);
            float4 gv = __ldg((const float4*)&g_gamma_h[((size_t)t * BB + row) * HH + c]);
            float4 o = make_float4(hv.x * gv.x, hv.y * gv.y, hv.z * gv.z, hv.w * gv.w);
            *(float4*)&sScr[i * 512 + c] = o;
            if (fh == 0) *(float4*)&g_hdec[(size_t)row * HH + c] = o;
        }
        __syncthreads();

        // thread (fl, kq): partial x_h over k-slice [kq*64, kq*64+64) for all 8 rows
        {
            float accs[8];
            #pragma unroll
            for (int r = 0; r < 8; r++) accs[r] = 0.f;
            const int kb = kq * 64;
            #pragma unroll
            for (int kk = 0; kk < 64; kk += 4) {
                float4 w = *(const float4*)&sWh[fl * 516 + kb + kk];
                #pragma unroll
                for (int r = 0; r < 8; r++) {
                    float4 h = *(const float4*)&sScr[r * 512 + kb + kk];
                    accs[r] += h.x * w.x + h.y * w.y + h.z * w.z + h.w * w.w;
                }
            }
            #pragma unroll
            for (int r = 0; r < 8; r++)
                sRed[kq * 512 + r * 64 + fl] = accs[r];
        }
        __syncthreads();

        float xh, m_, x_;
        size_t gofs;
        {
            xh = bhr;
            #pragma unroll
            for (int q = 0; q < 8; q++) xh += sRed[q * 512 + rO * 64 + fl];
            int row = r0g + rO;
            gofs = ((size_t)row * TT + t) * FF + fg;
            m_ = __ldg(&g_mf[gofs]);
            x_ = __ldg(&values[gofs]);
            g_xc[(size_t)row * FF + fg] = m_ * x_ + (1.f - m_) * xh;
        }
        gridbar(btgt);

        // ================= phase A2: z_h, c_h, c_c =================
        #pragma unroll
        for (int it = tid; it < 1024; it += NT) {
            int i = it >> 7; int c = it & 127;
            sScr[i * 128 + c] = __ldcg(&g_xc[(size_t)(r0g + i) * FF + c]);
        }
        __syncthreads();
        {
            float acz[8];
            #pragma unroll
            for (int r = 0; r < 8; r++) acz[r] = 0.f;
            const int kb = kq * 16;
            #pragma unroll
            for (int kk = 0; kk < 16; kk += 4) {
                float4 w = *(const float4*)&sWf[fl * 132 + kb + kk];
                #pragma unroll
                for (int r = 0; r < 8; r++) {
                    float4 xv = *(const float4*)&sScr[r * 128 + kb + kk];
                    acz[r] += xv.x * w.x + xv.y * w.y + xv.z * w.z + xv.w * w.w;
                }
            }
            #pragma unroll
            for (int r = 0; r < 8; r++)
                sRed[kq * 512 + r * 64 + fl] = acz[r];
        }
        __syncthreads();
        {
            float zh = bfr;
            #pragma unroll
            for (int q = 0; q < 8; q++) zh += sRed[q * 512 + rO * 64 + fl];
            float al = __ldg(&g_alpha[((size_t)t * BB + (r0g + rO)) * FF + fg]);
            float ch = al * zh + (1.f - al) * xh;
            out[gofs] = m_ * x_ + (1.f - m_) * ch;
        }
        gridbar(btgt);

        // ================= phase B: gates GEMM (bf16 mma) + LSTM =================
        float4 acc[2][2];
        #pragma unroll
        for (int i = 0; i < 2; i++)
            #pragma unroll
            for (int j = 0; j < 2; j++)
                acc[i][j] = make_float4(0.f, 0.f, 0.f, 0.f);

        stage_a_chunk(sAs, out, 0, m0, t, tid);
        __syncthreads();

        #pragma unroll 1
        for (int kc = 0; kc < 12; kc++) {
            const unsigned* As = sAs + (kc & 1) * (64 * 36);

            // B fragments: 4 x LDG.128 per thread (2 k-steps per uint4)
            uint4 bf[2][2];
            {
                const uint4* bp = &g_Bpk[(((size_t)ny * 16 + wc * 2) * 24 + kc * 2) * 32 + lane];
                #pragma unroll
                for (int nf = 0; nf < 2; nf++)
                    #pragma unroll
                    for (int q = 0; q < 2; q++)
                        bf[nf][q] = __ldg(&bp[((size_t)nf * 24 + q) * 32]);
            }
            if (kc < 11)
                stage_a_chunk(sAs + ((kc + 1) & 1) * (64 * 36), out, kc + 1, m0, t, tid);

            #pragma unroll
            for (int ks = 0; ks < 4; ks++) {       // 4 k16-steps per 64-k chunk
                int kb = ks * 8;                   // u32-pair offset
                unsigned a[2][4];
                #pragma unroll
                for (int mf = 0; mf < 2; mf++) {
                    int r = wm * 32 + mf * 16 + gID;
                    a[mf][0] = As[(r    ) * 36 + kb + tg];
                    a[mf][1] = As[(r + 8) * 36 + kb + tg];
                    a[mf][2] = As[(r    ) * 36 + kb + tg + 4];
                    a[mf][3] = As[(r + 8) * 36 + kb + tg + 4];
                }
                int q = ks >> 1;
                bool hi = (ks & 1) != 0;
                #pragma unroll
                for (int nf = 0; nf < 2; nf++) {
                    unsigned b0 = hi ? bf[nf][q].z : bf[nf][q].x;
                    unsigned b1 = hi ? bf[nf][q].w : bf[nf][q].y;
                    mma_bf16(acc[0][nf], a[0][0], a[0][1], a[0][2], a[0][3], b0, b1);
                    mma_bf16(acc[1][nf], a[1][0], a[1][1], a[1][2], a[1][3], b0, b1);
                }
            }
            __syncthreads();
        }

        // exchange gates so each thread sees i,f,g,o for its (m, unit)
        #pragma unroll
        for (int mf = 0; mf < 2; mf++) {
            int rbase = wm * 32 + mf * 16 + gID;
            #pragma unroll
            for (int nf = 0; nf < 2; nf++) {
                int cbase = wc * 16 + nf * 8 + tg * 2;
                sGs[(rbase    ) * 129 + cbase    ] = acc[mf][nf].x;
                sGs[(rbase    ) * 129 + cbase + 1] = acc[mf][nf].y;
                sGs[(rbase + 8) * 129 + cbase    ] = acc[mf][nf].z;
                sGs[(rbase + 8) * 129 + cbase + 1] = acc[mf][nf].w;
            }
        }
        __syncthreads();

        // fused LSTM pointwise update; c lives in registers
        #pragma unroll
        for (int j = 0; j < 4; j++) {
            int ml = wid + 16 * j;
            float ig  = sigf(sGs[ml * 129 +  0 + lane] + bi0);
            float fgt = sigf(sGs[ml * 129 + 32 + lane] + bi1);
            float gg  = tanhf(sGs[ml * 129 + 64 + lane] + bi2);
            float og  = sigf(sGs[ml * 129 + 96 + lane] + bi3);
            float cn = fgt * c_state[j] + ig * gg;
            c_state[j] = cn;
            g_h[(size_t)(m0 + ml) * HH + nEp] = og * tanhf(cn);
        }
        gridbar(btgt);
    }
}

// ---------------- launch ----------------
extern "C" void kernel_launch(void* const* d_in, const int* in_sizes, int n_in,
                              void* d_out, int out_size)
{
    const float* values = (const float*)d_in[0];
    const int*   masks  = (const int*)  d_in[1];
    const float* deltas = (const float*)d_in[2];
    const float* W_dh = (const float*)d_in[3];
    const float* b_dh = (const float*)d_in[4];
    const float* W_dx = (const float*)d_in[5];
    const float* b_dx = (const float*)d_in[6];
    const float* W_hr = (const float*)d_in[7];
    const float* b_hr = (const float*)d_in[8];
    const float* W_fr = (const float*)d_in[9];
    const float* b_fr = (const float*)d_in[10];
    const float* W_wc = (const float*)d_in[11];
    const float* b_wc = (const float*)d_in[12];
    const float* W_ih = (const float*)d_in[13];
    const float* W_hh = (const float*)d_in[14];
    const float* b_ih = (const float*)d_in[15];
    const float* b_hh = (const float*)d_in[16];
    float* out = (float*)d_out;

    const int SMEM_BYTES = (64 * 516 + 64 * 132 + 8704) * 4;   // 200704
    cudaFuncSetAttribute(loop_kernel, cudaFuncAttributeMaxDynamicSharedMemorySize, SMEM_BYTES);

    init_pack_kernel<<<8192, 256>>>(masks, W_ih, W_hh);                       // launch 1
    pre01_kernel<<<dim3(2048, 10), 256>>>(deltas, W_dh, b_dh, W_dx, b_dx);    // launch 2
    pre2_kernel<<<dim3(2048, 2), 256>>>(W_wc, b_wc);                          // launch 3
    loop_kernel<<<NCTA, NT, SMEM_BYTES>>>(values, W_hr, b_hr, W_fr, b_fr,     // launch 4 (profiled)
                                          b_ih, b_hh, out);
}